// round 15
// baseline (speedup 1.0000x reference)
#include <cuda_runtime.h>
#include <cstddef>

#define BB 256
#define TT 2048
#define NXX 64
#define NUU 32
#define NYY 16
#define HH 128

typedef unsigned long long u64;

// BAR_A: ALL 352 threads. B: full CTA __syncthreads.
#define BAR_A() asm volatile("bar.sync 1, 352;" ::: "memory")

// Packed fp32x2 helpers (per-lane IEEE fma.rn, identical to scalar fma.rn.f32).
__device__ __forceinline__ u64 pk2(float lo, float hi) {
    u64 r; asm("mov.b64 %0, {%1, %2};" : "=l"(r) : "f"(lo), "f"(hi)); return r;
}
__device__ __forceinline__ void upk2(u64 v, float& lo, float& hi) {
    asm("mov.b64 {%0, %1}, %2;" : "=f"(lo), "=f"(hi) : "l"(v));
}
__device__ __forceinline__ u64 fma2(u64 a, u64 b, u64 c) {
    u64 d; asm("fma.rn.f32x2 %0, %1, %2, %3;" : "=l"(d) : "l"(a), "l"(b), "l"(c)); return d;
}

// IEEE round-to-nearest divide, immune to fast-math substitution.
__device__ __forceinline__ float fdiv_rn(float a, float b) {
    float r; asm("div.rn.f32 %0, %1, %2;" : "=f"(r) : "f"(a), "f"(b)); return r;
}

// Exact replication of XLA EmitFastTanh (FMA-capable target). DO NOT TOUCH.
__device__ __forceinline__ float xla_tanh(float x) {
    const float kClamp = 7.99881172180175781f;
    float xc = fmaxf(-kClamp, fminf(x, kClamp));
    float x2 = __fmul_rn(xc, xc);
    float p = fmaf(x2, -2.76076847742355e-16f, 2.00018790482477e-13f);
    p = fmaf(x2, p, -8.60467152213735e-11f);
    p = fmaf(x2, p,  5.12229709037114e-08f);
    p = fmaf(x2, p,  1.48572235717979e-05f);
    p = fmaf(x2, p,  6.37261928875436e-04f);
    p = fmaf(x2, p,  4.89352455891786e-03f);
    float num = __fmul_rn(xc, p);
    float q = fmaf(x2, 1.19825839466702e-06f, 1.18534705686654e-04f);
    q = fmaf(x2, q, 2.26843463243900e-03f);
    q = fmaf(x2, q, 4.89352518554385e-03f);
    float r = fdiv_rn(num, q);
    return (fabsf(x) < 0.0004f) ? x : r;
}

// Packed dot (h-warps only — slack path): single per-lane chain, k ascending.
template <int NVEC>
__device__ __forceinline__ u64 dot_packed(const ulonglong2* __restrict__ src,
                                          const float* __restrict__ w) {
    u64 acc = pk2(0.f, 0.f);
    #pragma unroll
    for (int k2 = 0; k2 < NVEC; k2++) {
        const ulonglong2 v = src[k2];
        acc = fma2(v.x, pk2(w[2*k2+0], w[2*k2+0]), acc);
        acc = fma2(v.y, pk2(w[2*k2+1], w[2*k2+1]), acc);
    }
    return acc;
}

// 128 CTAs x 352 threads; 2 batch elements per CTA.
// Activation layout: float2 pairs (e0,e1) per k; float4 view = 2 consecutive k.
//   tid   0.. 31 : y-warp — scalar dot, phase 2, lagged 1 step.
//   tid  32..159 : h-warps — packed dot, phase 2 (A -> B).
//   tid 160..223 : dx-warps — SCALAR dual-chain 128-dot (critical), phase 2.
//   tid 224..351 : g-warps — SCALAR dual-chain 96-dot (critical), phase 1.
// Per-accumulator orders identical to R6-R14 passing kernels (bit-exact).

__global__ __launch_bounds__(352, 1)
void ssm_kernel(const float* __restrict__ x0,
                const float* __restrict__ u,
                const float* __restrict__ Wg1, const float* __restrict__ bg1,
                const float* __restrict__ Wg2, const float* __restrict__ bg2,
                const float* __restrict__ Wh1, const float* __restrict__ bh1,
                const float* __restrict__ Wh2, const float* __restrict__ bh2,
                float* __restrict__ out_x, float* __restrict__ out_y)
{
    __shared__ __align__(16) float2 sxu2[2][96];   // [parity][k] = (e0,e1); 0..63 x, 64..95 u
    __shared__ __align__(16) float2 g1s2[HH];      // tanh(g layer-1) pairs
    __shared__ __align__(16) float2 h1p2[2][HH];   // tanh(h layer-1) pairs, double buffer

    const int tid = threadIdx.x;
    const int b0  = blockIdx.x * 2;

    // ---- init: x0, u0 into parity-0 buffer as pairs ----
    if (tid < 64) {
        sxu2[0][tid] = make_float2(x0[(size_t)(b0 + 0) * NXX + tid],
                                   x0[(size_t)(b0 + 1) * NXX + tid]);
    } else if (tid < 96) {
        int k = tid - 64;
        sxu2[0][64 + k] = make_float2(u[(size_t)(b0 + 0) * TT * NUU + k],
                                      u[(size_t)(b0 + 1) * TT * NUU + k]);
    }

    if (tid >= 224) {
        // ===================== g-warps (phase-1 critical, scalar) ==================
        const int h = tid - 224;
        float wg1r[96];
        #pragma unroll
        for (int k = 0; k < 96; k++) wg1r[k] = Wg1[k * HH + h];
        const float bg1r = bg1[h];

        __syncthreads();  // init visible

        #pragma unroll 1
        for (int t = 0; t < TT; t++) {
            const int p = t & 1;
            const float4* x4 = (const float4*)&sxu2[p][0];  // v = {e0[2i],e1[2i],e0[2i+1],e1[2i+1]}

            float zg0 = 0.f, zg1 = 0.f;
            #pragma unroll
            for (int i = 0; i < 48; i++) {           // 2 k per iter, k ascending
                const float4 v = x4[i];
                zg0 = fmaf(v.x, wg1r[2*i+0], zg0);
                zg1 = fmaf(v.y, wg1r[2*i+0], zg1);
                zg0 = fmaf(v.z, wg1r[2*i+1], zg0);
                zg1 = fmaf(v.w, wg1r[2*i+1], zg1);
            }
            g1s2[h] = make_float2(xla_tanh(__fadd_rn(zg0, bg1r)),
                                  xla_tanh(__fadd_rn(zg1, bg1r)));
            BAR_A();          // g1 published -> phase 2 (dx + h + y) starts
            __syncthreads();  // B
        }
    } else if (tid >= 160) {
        // ===================== dx-warps (phase-2 critical, scalar) =================
        const int q = tid - 160;        // 0..63
        const int j = q;

        float wg2r[128];
        #pragma unroll
        for (int i = 0; i < 128; i++) wg2r[i] = Wg2[i * NXX + j];
        const float bg2r = bg2[j];

        const size_t u_base0 = (size_t)(b0 + 0) * TT * NUU + q;  // q<32 duty
        const size_t u_base1 = (size_t)(b0 + 1) * TT * NUU + q;

        float xr0 = x0[(size_t)(b0 + 0) * NXX + j];
        float xr1 = x0[(size_t)(b0 + 1) * NXX + j];
        float* oxp0 = out_x + (size_t)(b0 + 0) * TT * NXX + j;
        float* oxp1 = out_x + (size_t)(b0 + 1) * TT * NXX + j;

        __syncthreads();  // init visible

        const float4* g4 = (const float4*)&g1s2[0];

        #pragma unroll 1
        for (int t = 0; t < TT; t++) {
            const int pn = (t + 1) & 1;

            // ---- phase 1: launch u(t+1) loads first, then record x_t ----
            float un0 = 0.f, un1 = 0.f;
            if (q < 32) {
                int tn = (t + 1 < TT) ? (t + 1) : (TT - 1);
                un0 = u[u_base0 + (size_t)tn * NUU];
                un1 = u[u_base1 + (size_t)tn * NUU];
            }
            *oxp0 = xr0;  oxp0 += NXX;
            *oxp1 = xr1;  oxp1 += NXX;
            BAR_A();  // g1 ready

            // ---- phase 2: two interleaved scalar 128-dots (ascending i) ----
            float dxa0 = 0.f, dxa1 = 0.f;
            #pragma unroll
            for (int i = 0; i < 64; i++) {           // 2 i per iter
                const float4 v = g4[i];              // {g0[2i],g1[2i],g0[2i+1],g1[2i+1]}
                dxa0 = fmaf(v.x, wg2r[2*i+0], dxa0);
                dxa1 = fmaf(v.y, wg2r[2*i+0], dxa1);
                dxa0 = fmaf(v.z, wg2r[2*i+1], dxa0);
                dxa1 = fmaf(v.w, wg2r[2*i+1], dxa1);
            }
            // pinned HLO order: x_{t+1} = x + (dot + bg2)
            xr0 = __fadd_rn(xr0, __fadd_rn(dxa0, bg2r));
            xr1 = __fadd_rn(xr1, __fadd_rn(dxa1, bg2r));
            sxu2[pn][j] = make_float2(xr0, xr1);
            if (q < 32) sxu2[pn][64 + q] = make_float2(un0, un1);
            __syncthreads();  // B
        }
    } else if (tid >= 32) {
        // ===================== h-warps (phase-2 window, packed) ====================
        const int h = tid - 32;         // 0..127
        float wh1r[64];
        #pragma unroll
        for (int k = 0; k < 64; k++) wh1r[k] = Wh1[k * HH + h];
        const float bh1r = bh1[h];

        __syncthreads();  // init visible

        #pragma unroll 1
        for (int t = 0; t < TT; t++) {
            const int p = t & 1;
            BAR_A();  // enter phase 2

            const ulonglong2* x2 = (const ulonglong2*)&sxu2[p][0];
            u64 zh = dot_packed<32>(x2, wh1r);
            float zh0, zh1; upk2(zh, zh0, zh1);
            h1p2[p][h] = make_float2(xla_tanh(__fadd_rn(zh0, bh1r)),
                                     xla_tanh(__fadd_rn(zh1, bh1r)));
            __syncthreads();  // B: h1 committed with state
        }
    } else {
        // ====== y-warp: scalar dot, phase-2 window, lagged one step ==============
        const int oo = tid;             // 0..31
        const int e  = oo >> 4;         // element
        const int oc = oo & 15;         // output col

        float wh2r[128];
        #pragma unroll
        for (int i = 0; i < 128; i++) wh2r[i] = Wh2[i * NYY + oc];
        const float bh2r = bh2[oc];

        float* oyp = out_y + (size_t)(b0 + e) * TT * NYY + oc;

        __syncthreads();  // init visible

        #pragma unroll 1
        for (int t = 0; t < TT; t++) {
            BAR_A();  // enter phase 2; h1p[(t-1)&1] is stable (h writes [t&1])
            if (t > 0) {
                const int pp = (t - 1) & 1;
                const float4* h4 = (const float4*)&h1p2[pp][0];
                float ya = 0.0f;
                #pragma unroll
                for (int i2 = 0; i2 < 64; i2++) {
                    const float4 v = h4[i2];
                    float a0 = (e == 0) ? v.x : v.y;
                    float a1 = (e == 0) ? v.z : v.w;
                    ya = fmaf(a0, wh2r[2*i2+0], ya);
                    ya = fmaf(a1, wh2r[2*i2+1], ya);
                }
                oyp[(size_t)(t - 1) * NYY] = __fadd_rn(ya, bh2r);
            }
            __syncthreads();  // B
        }
        // drain: y(TT-1)
        {
            const int pp = (TT - 1) & 1;
            const float4* h4 = (const float4*)&h1p2[pp][0];
            float ya = 0.0f;
            #pragma unroll
            for (int i2 = 0; i2 < 64; i2++) {
                const float4 v = h4[i2];
                float a0 = (e == 0) ? v.x : v.y;
                float a1 = (e == 0) ? v.z : v.w;
                ya = fmaf(a0, wh2r[2*i2+0], ya);
                ya = fmaf(a1, wh2r[2*i2+1], ya);
            }
            oyp[(size_t)(TT - 1) * NYY] = __fadd_rn(ya, bh2r);
        }
    }
}

extern "C" void kernel_launch(void* const* d_in, const int* in_sizes, int n_in,
                              void* d_out, int out_size)
{
    const float* x0  = (const float*)d_in[0];
    const float* u   = (const float*)d_in[1];
    const float* Wg1 = (const float*)d_in[2];
    const float* bg1 = (const float*)d_in[3];
    const float* Wg2 = (const float*)d_in[4];
    const float* bg2 = (const float*)d_in[5];
    const float* Wh1 = (const float*)d_in[6];
    const float* bh1 = (const float*)d_in[7];
    const float* Wh2 = (const float*)d_in[8];
    const float* bh2 = (const float*)d_in[9];

    float* out_x = (float*)d_out;
    float* out_y = out_x + (size_t)BB * TT * NXX;

    ssm_kernel<<<BB / 2, 352>>>(x0, u, Wg1, bg1, Wg2, bg2,
                                Wh1, bh1, Wh2, bh2, out_x, out_y);
}

// round 16
// speedup vs baseline: 1.2044x; 1.2044x over previous
#include <cuda_runtime.h>
#include <cstddef>

#define BB 256
#define TT 2048
#define NXX 64
#define NUU 32
#define NYY 16
#define HH 128

typedef unsigned long long u64;

// BAR_A: all 288 threads. B: full CTA __syncthreads (288).
#define BAR_A() asm volatile("bar.sync 1, 288;" ::: "memory")

// Packed fp32x2 helpers (per-lane IEEE fma.rn, identical to scalar fma.rn.f32).
__device__ __forceinline__ u64 pk2(float lo, float hi) {
    u64 r; asm("mov.b64 %0, {%1, %2};" : "=l"(r) : "f"(lo), "f"(hi)); return r;
}
__device__ __forceinline__ void upk2(u64 v, float& lo, float& hi) {
    asm("mov.b64 {%0, %1}, %2;" : "=f"(lo), "=f"(hi) : "l"(v));
}
__device__ __forceinline__ u64 fma2(u64 a, u64 b, u64 c) {
    u64 d; asm("fma.rn.f32x2 %0, %1, %2, %3;" : "=l"(d) : "l"(a), "l"(b), "l"(c)); return d;
}

// IEEE round-to-nearest divide, immune to fast-math substitution.
__device__ __forceinline__ float fdiv_rn(float a, float b) {
    float r; asm("div.rn.f32 %0, %1, %2;" : "=f"(r) : "f"(a), "f"(b)); return r;
}

// Exact replication of XLA EmitFastTanh (FMA-capable target). DO NOT TOUCH.
__device__ __forceinline__ float xla_tanh(float x) {
    const float kClamp = 7.99881172180175781f;
    float xc = fmaxf(-kClamp, fminf(x, kClamp));
    float x2 = __fmul_rn(xc, xc);
    float p = fmaf(x2, -2.76076847742355e-16f, 2.00018790482477e-13f);
    p = fmaf(x2, p, -8.60467152213735e-11f);
    p = fmaf(x2, p,  5.12229709037114e-08f);
    p = fmaf(x2, p,  1.48572235717979e-05f);
    p = fmaf(x2, p,  6.37261928875436e-04f);
    p = fmaf(x2, p,  4.89352455891786e-03f);
    float num = __fmul_rn(xc, p);
    float q = fmaf(x2, 1.19825839466702e-06f, 1.18534705686654e-04f);
    q = fmaf(x2, q, 2.26843463243900e-03f);
    q = fmaf(x2, q, 4.89352518554385e-03f);
    float r = fdiv_rn(num, q);
    return (fabsf(x) < 0.0004f) ? x : r;
}

// Packed dot: single per-lane chain, k ascending — bit-identical to scalar loop.
template <int NVEC>
__device__ __forceinline__ u64 dot_packed(const ulonglong2* __restrict__ src,
                                          const float* __restrict__ w) {
    u64 acc = pk2(0.f, 0.f);
    #pragma unroll
    for (int k2 = 0; k2 < NVEC; k2++) {
        const ulonglong2 v = src[k2];
        acc = fma2(v.x, pk2(w[2*k2+0], w[2*k2+0]), acc);
        acc = fma2(v.y, pk2(w[2*k2+1], w[2*k2+1]), acc);
    }
    return acc;
}

// 128 CTAs x 288 threads (9 warps); 2 batch elements per CTA, packed lane-wise.
// SMSP-collision-free phase layout (wid%4):
//   wid 0 (tid   0.. 31): y-warp, SMSP0 — scalar dot, phase 2, lagged 1 step.
//   wid 1-2 (tid 32.. 95): h-warps, SMSP1/2 — 2 h-columns per thread, phase 2.
//   wid 3-4 (tid 96..159): dx-warps, SMSP3/0 — packed 128-dot, phase 2 critical.
//   wid 5-8 (tid160..287): g-warps, SMSP1,2,3,0 — packed 96-dot, phase 1 critical.
// Phase 1: one g-warp per SMSP, alone. Phase 2: dx SMSPs host no h-warp.
// All accumulation orders identical to the R14 passing kernel (bit-exact).

__global__ __launch_bounds__(288, 1)
void ssm_kernel(const float* __restrict__ x0,
                const float* __restrict__ u,
                const float* __restrict__ Wg1, const float* __restrict__ bg1,
                const float* __restrict__ Wg2, const float* __restrict__ bg2,
                const float* __restrict__ Wh1, const float* __restrict__ bh1,
                const float* __restrict__ Wh2, const float* __restrict__ bh2,
                float* __restrict__ out_x, float* __restrict__ out_y)
{
    __shared__ __align__(16) float2 sxu2[2][96];   // [parity][k] = (e0,e1); 0..63 x, 64..95 u
    __shared__ __align__(16) float2 g1s2[HH];      // tanh(g layer-1) pairs
    __shared__ __align__(16) float2 h1p2[2][HH];   // tanh(h layer-1) pairs, double buffer

    const int tid = threadIdx.x;
    const int b0  = blockIdx.x * 2;

    // ---- init: x0, u0 into parity-0 buffer as pairs ----
    if (tid < 64) {
        sxu2[0][tid] = make_float2(x0[(size_t)(b0 + 0) * NXX + tid],
                                   x0[(size_t)(b0 + 1) * NXX + tid]);
    } else if (tid < 96) {
        int k = tid - 64;
        sxu2[0][64 + k] = make_float2(u[(size_t)(b0 + 0) * TT * NUU + k],
                                      u[(size_t)(b0 + 1) * TT * NUU + k]);
    }

    if (tid >= 160) {
        // ===================== g-warps (phase-1 critical, packed) ==================
        const int h = tid - 160;
        float wg1r[96];
        #pragma unroll
        for (int k = 0; k < 96; k++) wg1r[k] = Wg1[k * HH + h];
        const float bg1r = bg1[h];

        __syncthreads();  // init visible

        #pragma unroll 1
        for (int t = 0; t < TT; t++) {
            const int p = t & 1;
            const ulonglong2* x2 = (const ulonglong2*)&sxu2[p][0];

            u64 zg = dot_packed<48>(x2, wg1r);
            float zg0, zg1; upk2(zg, zg0, zg1);
            g1s2[h] = make_float2(xla_tanh(__fadd_rn(zg0, bg1r)),
                                  xla_tanh(__fadd_rn(zg1, bg1r)));
            BAR_A();          // g1 published -> phase 2 (dx + h + y) starts
            __syncthreads();  // B
        }
    } else if (tid >= 96) {
        // ===================== dx-warps (phase-2 critical, packed) =================
        const int q = tid - 96;         // 0..63
        const int j = q;

        float wg2r[128];
        #pragma unroll
        for (int i = 0; i < 128; i++) wg2r[i] = Wg2[i * NXX + j];
        const float bg2r = bg2[j];

        const size_t u_base0 = (size_t)(b0 + 0) * TT * NUU + q;  // q<32 duty
        const size_t u_base1 = (size_t)(b0 + 1) * TT * NUU + q;

        float xr0 = x0[(size_t)(b0 + 0) * NXX + j];
        float xr1 = x0[(size_t)(b0 + 1) * NXX + j];
        float* oxp0 = out_x + (size_t)(b0 + 0) * TT * NXX + j;
        float* oxp1 = out_x + (size_t)(b0 + 1) * TT * NXX + j;

        __syncthreads();  // init visible

        const ulonglong2* g2 = (const ulonglong2*)&g1s2[0];

        #pragma unroll 1
        for (int t = 0; t < TT; t++) {
            const int pn = (t + 1) & 1;

            // ---- phase 1: launch u(t+1) loads first, then record x_t ----
            float un0 = 0.f, un1 = 0.f;
            if (q < 32) {
                int tn = (t + 1 < TT) ? (t + 1) : (TT - 1);
                un0 = u[u_base0 + (size_t)tn * NUU];
                un1 = u[u_base1 + (size_t)tn * NUU];
            }
            *oxp0 = xr0;  oxp0 += NXX;
            *oxp1 = xr1;  oxp1 += NXX;
            BAR_A();  // g1 ready

            // ---- phase 2: packed sequential 128-dot (ascending i) ----
            u64 dxa = dot_packed<64>(g2, wg2r);
            float dxa0, dxa1; upk2(dxa, dxa0, dxa1);
            // pinned HLO order: x_{t+1} = x + (dot + bg2)
            xr0 = __fadd_rn(xr0, __fadd_rn(dxa0, bg2r));
            xr1 = __fadd_rn(xr1, __fadd_rn(dxa1, bg2r));
            sxu2[pn][j] = make_float2(xr0, xr1);
            if (q < 32) sxu2[pn][64 + q] = make_float2(un0, un1);
            __syncthreads();  // B
        }
    } else if (tid >= 32) {
        // ======= h-warps (phase 2, packed; 2 h-columns per thread) ================
        const int lane = tid & 31;
        const int hw   = (tid >> 5) - 1;     // 0..1
        const int c0   = hw * 32 + lane;     // 0..63
        const int c1   = c0 + 64;            // 64..127

        float wh1a[64];
        float wh1b[64];
        #pragma unroll
        for (int k = 0; k < 64; k++) wh1a[k] = Wh1[k * HH + c0];
        #pragma unroll
        for (int k = 0; k < 64; k++) wh1b[k] = Wh1[k * HH + c1];
        const float bh1a = bh1[c0];
        const float bh1b = bh1[c1];

        __syncthreads();  // init visible

        #pragma unroll 1
        for (int t = 0; t < TT; t++) {
            const int p = t & 1;
            BAR_A();  // enter phase 2

            const ulonglong2* x2 = (const ulonglong2*)&sxu2[p][0];
            u64 zha = dot_packed<32>(x2, wh1a);
            u64 zhb = dot_packed<32>(x2, wh1b);
            float za0, za1, zb0, zb1;
            upk2(zha, za0, za1);
            upk2(zhb, zb0, zb1);
            h1p2[p][c0] = make_float2(xla_tanh(__fadd_rn(za0, bh1a)),
                                      xla_tanh(__fadd_rn(za1, bh1a)));
            h1p2[p][c1] = make_float2(xla_tanh(__fadd_rn(zb0, bh1b)),
                                      xla_tanh(__fadd_rn(zb1, bh1b)));
            __syncthreads();  // B: h1 committed with state
        }
    } else {
        // ====== y-warp: scalar dot, phase-2 window, lagged one step ==============
        const int oo = tid;             // 0..31
        const int e  = oo >> 4;         // element
        const int oc = oo & 15;         // output col

        float wh2r[128];
        #pragma unroll
        for (int i = 0; i < 128; i++) wh2r[i] = Wh2[i * NYY + oc];
        const float bh2r = bh2[oc];

        float* oyp = out_y + (size_t)(b0 + e) * TT * NYY + oc;

        __syncthreads();  // init visible

        #pragma unroll 1
        for (int t = 0; t < TT; t++) {
            BAR_A();  // enter phase 2; h1p[(t-1)&1] is stable (h writes [t&1])
            if (t > 0) {
                const int pp = (t - 1) & 1;
                const float4* h4 = (const float4*)&h1p2[pp][0];
                float ya = 0.0f;
                #pragma unroll
                for (int i2 = 0; i2 < 64; i2++) {
                    const float4 v = h4[i2];
                    float a0 = (e == 0) ? v.x : v.y;
                    float a1 = (e == 0) ? v.z : v.w;
                    ya = fmaf(a0, wh2r[2*i2+0], ya);
                    ya = fmaf(a1, wh2r[2*i2+1], ya);
                }
                oyp[(size_t)(t - 1) * NYY] = __fadd_rn(ya, bh2r);
            }
            __syncthreads();  // B
        }
        // drain: y(TT-1)
        {
            const int pp = (TT - 1) & 1;
            const float4* h4 = (const float4*)&h1p2[pp][0];
            float ya = 0.0f;
            #pragma unroll
            for (int i2 = 0; i2 < 64; i2++) {
                const float4 v = h4[i2];
                float a0 = (e == 0) ? v.x : v.y;
                float a1 = (e == 0) ? v.z : v.w;
                ya = fmaf(a0, wh2r[2*i2+0], ya);
                ya = fmaf(a1, wh2r[2*i2+1], ya);
            }
            oyp[(size_t)(TT - 1) * NYY] = __fadd_rn(ya, bh2r);
        }
    }
}

extern "C" void kernel_launch(void* const* d_in, const int* in_sizes, int n_in,
                              void* d_out, int out_size)
{
    const float* x0  = (const float*)d_in[0];
    const float* u   = (const float*)d_in[1];
    const float* Wg1 = (const float*)d_in[2];
    const float* bg1 = (const float*)d_in[3];
    const float* Wg2 = (const float*)d_in[4];
    const float* bg2 = (const float*)d_in[5];
    const float* Wh1 = (const float*)d_in[6];
    const float* bh1 = (const float*)d_in[7];
    const float* Wh2 = (const float*)d_in[8];
    const float* bh2 = (const float*)d_in[9];

    float* out_x = (float*)d_out;
    float* out_y = out_x + (size_t)BB * TT * NXX;

    ssm_kernel<<<BB / 2, 288>>>(x0, u, Wg1, bg1, Wg2, bg2,
                                Wh1, bh1, Wh2, bh2, out_x, out_y);
}

// round 17
// speedup vs baseline: 1.2358x; 1.0260x over previous
#include <cuda_runtime.h>
#include <cstddef>

#define BB 256
#define TT 2048
#define NXX 64
#define NUU 32
#define NYY 16
#define HH 128

typedef unsigned long long u64;

// BAR_A: all 288 threads. B: full CTA __syncthreads (288).
#define BAR_A() asm volatile("bar.sync 1, 288;" ::: "memory")

// Packed fp32x2 helpers (per-lane IEEE fma.rn, identical to scalar fma.rn.f32).
__device__ __forceinline__ u64 pk2(float lo, float hi) {
    u64 r; asm("mov.b64 %0, {%1, %2};" : "=l"(r) : "f"(lo), "f"(hi)); return r;
}
__device__ __forceinline__ void upk2(u64 v, float& lo, float& hi) {
    asm("mov.b64 {%0, %1}, %2;" : "=f"(lo), "=f"(hi) : "l"(v));
}
__device__ __forceinline__ u64 fma2(u64 a, u64 b, u64 c) {
    u64 d; asm("fma.rn.f32x2 %0, %1, %2, %3;" : "=l"(d) : "l"(a), "l"(b), "l"(c)); return d;
}

// IEEE round-to-nearest divide, immune to fast-math substitution.
__device__ __forceinline__ float fdiv_rn(float a, float b) {
    float r; asm("div.rn.f32 %0, %1, %2;" : "=f"(r) : "f"(a), "f"(b)); return r;
}

// Exact replication of XLA EmitFastTanh (FMA-capable target). DO NOT TOUCH.
__device__ __forceinline__ float xla_tanh(float x) {
    const float kClamp = 7.99881172180175781f;
    float xc = fmaxf(-kClamp, fminf(x, kClamp));
    float x2 = __fmul_rn(xc, xc);
    float p = fmaf(x2, -2.76076847742355e-16f, 2.00018790482477e-13f);
    p = fmaf(x2, p, -8.60467152213735e-11f);
    p = fmaf(x2, p,  5.12229709037114e-08f);
    p = fmaf(x2, p,  1.48572235717979e-05f);
    p = fmaf(x2, p,  6.37261928875436e-04f);
    p = fmaf(x2, p,  4.89352455891786e-03f);
    float num = __fmul_rn(xc, p);
    float q = fmaf(x2, 1.19825839466702e-06f, 1.18534705686654e-04f);
    q = fmaf(x2, q, 2.26843463243900e-03f);
    q = fmaf(x2, q, 4.89352518554385e-03f);
    float r = fdiv_rn(num, q);
    return (fabsf(x) < 0.0004f) ? x : r;
}

// Packed dot: single per-lane chain, k ascending — bit-identical to scalar loop.
template <int NVEC>
__device__ __forceinline__ u64 dot_packed(const ulonglong2* __restrict__ src,
                                          const float* __restrict__ w) {
    u64 acc = pk2(0.f, 0.f);
    #pragma unroll
    for (int k2 = 0; k2 < NVEC; k2++) {
        const ulonglong2 v = src[k2];
        acc = fma2(v.x, pk2(w[2*k2+0], w[2*k2+0]), acc);
        acc = fma2(v.y, pk2(w[2*k2+1], w[2*k2+1]), acc);
    }
    return acc;
}

// Scalar 128-dot over stride-2 smem floats (y-warp): single accumulator,
// k ascending — bit-identical values/order to the previous FSEL form.
__device__ __forceinline__ float dot_stride2(const float* __restrict__ hbase,
                                             const float* __restrict__ w) {
    float acc = 0.0f;
    #pragma unroll
    for (int k = 0; k < 128; k++)
        acc = fmaf(hbase[2*k], w[k], acc);
    return acc;
}

// 128 CTAs x 288 threads (9 warps); 2 batch elements per CTA, packed lane-wise.
//   wid 0 (tid   0.. 31): y-warp, SMSP0 — stride-2 scalar dot, phase 2, lagged.
//   wid 1-2 (tid 32.. 95): h-warps, SMSP1/2 — 2 h-columns per thread, phase 2.
//   wid 3-4 (tid 96..159): dx-warps, SMSP3/0 — packed 128-dot, phase 2 critical.
//   wid 5-8 (tid160..287): g-warps, SMSP1,2,3,0 — packed 96-dot, phase 1 critical.
// t-loop unrolled x2 with parity constant-folded. All accumulation orders
// identical to the R16 passing kernel (bit-exact).

__global__ __launch_bounds__(288, 1)
void ssm_kernel(const float* __restrict__ x0,
                const float* __restrict__ u,
                const float* __restrict__ Wg1, const float* __restrict__ bg1,
                const float* __restrict__ Wg2, const float* __restrict__ bg2,
                const float* __restrict__ Wh1, const float* __restrict__ bh1,
                const float* __restrict__ Wh2, const float* __restrict__ bh2,
                float* __restrict__ out_x, float* __restrict__ out_y)
{
    __shared__ __align__(16) float2 sxu2[2][96];   // [parity][k] = (e0,e1); 0..63 x, 64..95 u
    __shared__ __align__(16) float2 g1s2[HH];      // tanh(g layer-1) pairs
    __shared__ __align__(16) float2 h1p2[2][HH];   // tanh(h layer-1) pairs, double buffer

    const int tid = threadIdx.x;
    const int b0  = blockIdx.x * 2;

    // ---- init: x0, u0 into parity-0 buffer as pairs ----
    if (tid < 64) {
        sxu2[0][tid] = make_float2(x0[(size_t)(b0 + 0) * NXX + tid],
                                   x0[(size_t)(b0 + 1) * NXX + tid]);
    } else if (tid < 96) {
        int k = tid - 64;
        sxu2[0][64 + k] = make_float2(u[(size_t)(b0 + 0) * TT * NUU + k],
                                      u[(size_t)(b0 + 1) * TT * NUU + k]);
    }

    if (tid >= 160) {
        // ===================== g-warps (phase-1 critical, packed) ==================
        const int h = tid - 160;
        float wg1r[96];
        #pragma unroll
        for (int k = 0; k < 96; k++) wg1r[k] = Wg1[k * HH + h];
        const float bg1r = bg1[h];

        __syncthreads();  // init visible

        const ulonglong2* x2p0 = (const ulonglong2*)&sxu2[0][0];
        const ulonglong2* x2p1 = (const ulonglong2*)&sxu2[1][0];

        #pragma unroll 1
        for (int t = 0; t < TT; t += 2) {
            {   // t even: parity 0
                u64 zg = dot_packed<48>(x2p0, wg1r);
                float zg0, zg1; upk2(zg, zg0, zg1);
                g1s2[h] = make_float2(xla_tanh(__fadd_rn(zg0, bg1r)),
                                      xla_tanh(__fadd_rn(zg1, bg1r)));
                BAR_A();
                __syncthreads();
            }
            {   // t+1 odd: parity 1
                u64 zg = dot_packed<48>(x2p1, wg1r);
                float zg0, zg1; upk2(zg, zg0, zg1);
                g1s2[h] = make_float2(xla_tanh(__fadd_rn(zg0, bg1r)),
                                      xla_tanh(__fadd_rn(zg1, bg1r)));
                BAR_A();
                __syncthreads();
            }
        }
    } else if (tid >= 96) {
        // ===================== dx-warps (phase-2 critical, packed) =================
        const int q = tid - 96;         // 0..63
        const int j = q;

        float wg2r[128];
        #pragma unroll
        for (int i = 0; i < 128; i++) wg2r[i] = Wg2[i * NXX + j];
        const float bg2r = bg2[j];

        const size_t u_base0 = (size_t)(b0 + 0) * TT * NUU + q;  // q<32 duty
        const size_t u_base1 = (size_t)(b0 + 1) * TT * NUU + q;

        float xr0 = x0[(size_t)(b0 + 0) * NXX + j];
        float xr1 = x0[(size_t)(b0 + 1) * NXX + j];
        float* oxp0 = out_x + (size_t)(b0 + 0) * TT * NXX + j;
        float* oxp1 = out_x + (size_t)(b0 + 1) * TT * NXX + j;

        __syncthreads();  // init visible

        const ulonglong2* g2 = (const ulonglong2*)&g1s2[0];

        #pragma unroll 1
        for (int t = 0; t < TT; t += 2) {
            {   // step t (even): writes parity 1
                float un0 = 0.f, un1 = 0.f;
                if (q < 32) {
                    int tn = t + 1;   // t even < TT-1 always (TT even)
                    un0 = u[u_base0 + (size_t)tn * NUU];
                    un1 = u[u_base1 + (size_t)tn * NUU];
                }
                *oxp0 = xr0;  oxp0 += NXX;
                *oxp1 = xr1;  oxp1 += NXX;
                BAR_A();

                u64 dxa = dot_packed<64>(g2, wg2r);
                float dxa0, dxa1; upk2(dxa, dxa0, dxa1);
                xr0 = __fadd_rn(xr0, __fadd_rn(dxa0, bg2r));
                xr1 = __fadd_rn(xr1, __fadd_rn(dxa1, bg2r));
                sxu2[1][j] = make_float2(xr0, xr1);
                if (q < 32) sxu2[1][64 + q] = make_float2(un0, un1);
                __syncthreads();
            }
            {   // step t+1 (odd): writes parity 0
                float un0 = 0.f, un1 = 0.f;
                if (q < 32) {
                    int tn = (t + 2 < TT) ? (t + 2) : (TT - 1);
                    un0 = u[u_base0 + (size_t)tn * NUU];
                    un1 = u[u_base1 + (size_t)tn * NUU];
                }
                *oxp0 = xr0;  oxp0 += NXX;
                *oxp1 = xr1;  oxp1 += NXX;
                BAR_A();

                u64 dxa = dot_packed<64>(g2, wg2r);
                float dxa0, dxa1; upk2(dxa, dxa0, dxa1);
                xr0 = __fadd_rn(xr0, __fadd_rn(dxa0, bg2r));
                xr1 = __fadd_rn(xr1, __fadd_rn(dxa1, bg2r));
                sxu2[0][j] = make_float2(xr0, xr1);
                if (q < 32) sxu2[0][64 + q] = make_float2(un0, un1);
                __syncthreads();
            }
        }
    } else if (tid >= 32) {
        // ======= h-warps (phase 2, packed; 2 h-columns per thread) ================
        const int lane = tid & 31;
        const int hw   = (tid >> 5) - 1;     // 0..1
        const int c0   = hw * 32 + lane;     // 0..63
        const int c1   = c0 + 64;            // 64..127

        float wh1a[64];
        float wh1b[64];
        #pragma unroll
        for (int k = 0; k < 64; k++) wh1a[k] = Wh1[k * HH + c0];
        #pragma unroll
        for (int k = 0; k < 64; k++) wh1b[k] = Wh1[k * HH + c1];
        const float bh1a = bh1[c0];
        const float bh1b = bh1[c1];

        __syncthreads();  // init visible

        const ulonglong2* x2p0 = (const ulonglong2*)&sxu2[0][0];
        const ulonglong2* x2p1 = (const ulonglong2*)&sxu2[1][0];

        #pragma unroll 1
        for (int t = 0; t < TT; t += 2) {
            {   // parity 0
                BAR_A();
                u64 zha = dot_packed<32>(x2p0, wh1a);
                u64 zhb = dot_packed<32>(x2p0, wh1b);
                float za0, za1, zb0, zb1;
                upk2(zha, za0, za1);
                upk2(zhb, zb0, zb1);
                h1p2[0][c0] = make_float2(xla_tanh(__fadd_rn(za0, bh1a)),
                                          xla_tanh(__fadd_rn(za1, bh1a)));
                h1p2[0][c1] = make_float2(xla_tanh(__fadd_rn(zb0, bh1b)),
                                          xla_tanh(__fadd_rn(zb1, bh1b)));
                __syncthreads();
            }
            {   // parity 1
                BAR_A();
                u64 zha = dot_packed<32>(x2p1, wh1a);
                u64 zhb = dot_packed<32>(x2p1, wh1b);
                float za0, za1, zb0, zb1;
                upk2(zha, za0, za1);
                upk2(zhb, zb0, zb1);
                h1p2[1][c0] = make_float2(xla_tanh(__fadd_rn(za0, bh1a)),
                                          xla_tanh(__fadd_rn(za1, bh1a)));
                h1p2[1][c1] = make_float2(xla_tanh(__fadd_rn(zb0, bh1b)),
                                          xla_tanh(__fadd_rn(zb1, bh1b)));
                __syncthreads();
            }
        }
    } else {
        // ====== y-warp: stride-2 scalar dot, phase-2 window, lagged one step ======
        const int oo = tid;             // 0..31
        const int e  = oo >> 4;         // element
        const int oc = oo & 15;         // output col

        float wh2r[128];
        #pragma unroll
        for (int i = 0; i < 128; i++) wh2r[i] = Wh2[i * NYY + oc];
        const float bh2r = bh2[oc];

        float* oyp = out_y + (size_t)(b0 + e) * TT * NYY + oc;

        __syncthreads();  // init visible

        const float* hb0 = &h1p2[0][0].x + e;   // stride-2 view of element e
        const float* hb1 = &h1p2[1][0].x + e;

        #pragma unroll 1
        for (int t = 0; t < TT; t += 2) {
            {   // step t (even): y(t-1) from parity 1 (skip at t==0)
                BAR_A();
                if (t > 0) {
                    float ya = dot_stride2(hb1, wh2r);
                    oyp[(size_t)(t - 1) * NYY] = __fadd_rn(ya, bh2r);
                }
                __syncthreads();
            }
            {   // step t+1 (odd): y(t) from parity 0
                BAR_A();
                float ya = dot_stride2(hb0, wh2r);
                oyp[(size_t)t * NYY] = __fadd_rn(ya, bh2r);
                __syncthreads();
            }
        }
        // drain: y(TT-1) from parity (TT-1)&1 == 1 (no further writers)
        {
            float ya = dot_stride2(hb1, wh2r);
            oyp[(size_t)(TT - 1) * NYY] = __fadd_rn(ya, bh2r);
        }
    }
}

extern "C" void kernel_launch(void* const* d_in, const int* in_sizes, int n_in,
                              void* d_out, int out_size)
{
    const float* x0  = (const float*)d_in[0];
    const float* u   = (const float*)d_in[1];
    const float* Wg1 = (const float*)d_in[2];
    const float* bg1 = (const float*)d_in[3];
    const float* Wg2 = (const float*)d_in[4];
    const float* bg2 = (const float*)d_in[5];
    const float* Wh1 = (const float*)d_in[6];
    const float* bh1 = (const float*)d_in[7];
    const float* Wh2 = (const float*)d_in[8];
    const float* bh2 = (const float*)d_in[9];

    float* out_x = (float*)d_out;
    float* out_y = out_x + (size_t)BB * TT * NXX;

    ssm_kernel<<<BB / 2, 288>>>(x0, u, Wg1, bg1, Wg2, bg2,
                                Wh1, bh1, Wh2, bh2, out_x, out_y);
}